// round 1
// baseline (speedup 1.0000x reference)
#include <cuda_runtime.h>
#include <cstdint>
#include <math.h>

// Problem dims
#define BNROWS 32768   // B*N
#define DDIM   256
#define KCODES 1024

// Output layout (float32, concatenated in reference return order)
#define OFF_Q      0ull                  // 32768*256 = 8388608
#define OFF_DICT   8388608ull
#define OFF_COMMIT 8388609ull
#define OFF_IDX    8388610ull            // 32768
#define OFF_PERP   8421378ull

// ---------------- scratch (device globals; no allocations allowed) ----------
__device__ float  g_partS [256][DDIM];
__device__ float  g_partS2[256][DDIM];
__device__ float  g_partC [256];
__device__ float  g_cnt;
__device__ float  g_scale[DDIM];
__device__ float  g_shift[DDIM];
__device__ float  g_xb[(size_t)BNROWS * DDIM];   // normalized rows
__device__ float  g_ET[(size_t)KCODES * DDIM];   // codebook transposed [K][D]
__device__ float  g_csq[KCODES];                 // ||e_k||^2
__device__ int    g_idx[BNROWS];
__device__ float  g_counts[KCODES];
__device__ double g_loss;

// ---------------- K0: zero per-run accumulators -----------------------------
__global__ void k_zero() {
    int i = blockIdx.x * 256 + threadIdx.x;
    if (i < KCODES) g_counts[i] = 0.f;
    if (i == 0) g_loss = 0.0;
}

// ---------------- K1: masked per-column partial sums (deterministic) --------
__global__ void k_stats(const float* __restrict__ x, const int* __restrict__ mask) {
    int d = threadIdx.x;
    int b = blockIdx.x;
    int r0 = b * 128;
    float s = 0.f, s2 = 0.f, c = 0.f;
    for (int r = 0; r < 128; r++) {
        int m = mask[r0 + r];
        float v = x[(size_t)(r0 + r) * DDIM + d];
        if (m) { s += v; s2 += v * v; c += 1.f; }
    }
    g_partS [b][d] = s;
    g_partS2[b][d] = s2;
    if (d == 0) g_partC[b] = c;
}

// ---------------- K2: reduce stats -> scale/shift ----------------------------
__global__ void k_reduce_stats(const float* __restrict__ gamma, const float* __restrict__ beta) {
    int d = threadIdx.x;
    float s = 0.f, s2 = 0.f, cnt = 0.f;
    for (int b = 0; b < 256; b++) {
        s  += g_partS [b][d];
        s2 += g_partS2[b][d];
        cnt += g_partC[b];
    }
    if (d == 0) g_cnt = cnt;
    float nv = fmaxf(cnt, 1.f);
    float mu  = s / nv;
    float var = s2 / nv - mu * mu;
    float sc  = rsqrtf(var + 1e-5f) * gamma[d];
    g_scale[d] = sc;
    g_shift[d] = beta[d] - mu * sc;
}

// ---------------- K3: xb = x*scale + shift -----------------------------------
__global__ void k_norm(const float* __restrict__ x) {
    int d = threadIdx.x;
    size_t i = (size_t)blockIdx.x * DDIM + d;
    g_xb[i] = x[i] * g_scale[d] + g_shift[d];
}

// ---------------- K4: transpose E [D][K] -> ET [K][D] ------------------------
__global__ void k_transpose(const float* __restrict__ E) {
    __shared__ float t[32][33];
    int x0 = blockIdx.x * 32;  // code
    int y0 = blockIdx.y * 32;  // d
    for (int j = threadIdx.y; j < 32; j += 8)
        t[j][threadIdx.x] = E[(size_t)(y0 + j) * KCODES + x0 + threadIdx.x];
    __syncthreads();
    for (int j = threadIdx.y; j < 32; j += 8)
        g_ET[(size_t)(x0 + j) * DDIM + y0 + threadIdx.x] = t[threadIdx.x][j];
}

// ---------------- K5: code squared norms -------------------------------------
__global__ void k_csq() {
    int c = blockIdx.x;
    float v = g_ET[(size_t)c * DDIM + threadIdx.x];
    float s = v * v;
    for (int o = 16; o; o >>= 1) s += __shfl_down_sync(0xffffffffu, s, o);
    __shared__ float red[8];
    if ((threadIdx.x & 31) == 0) red[threadIdx.x >> 5] = s;
    __syncthreads();
    if (threadIdx.x < 8) {
        float t = red[threadIdx.x];
        for (int o = 4; o; o >>= 1) t += __shfl_down_sync(0xffu, t, o);
        if (threadIdx.x == 0) g_csq[c] = t;
    }
}

// ---------------- K6: fused GEMM + argmin (the hot kernel) -------------------
// Block: 128 rows x all 1024 codes (8 tiles of 128). 256 threads, 8x8 per thread.
// f32x2 packed FMAs double the FFMA pipe rate. Double-buffered smem.
__global__ __launch_bounds__(256, 2) void k_argmin(const float* __restrict__ E) {
    const int tid = threadIdx.x;
    const int tx = tid & 15;         // code group
    const int ty = tid >> 4;         // row group
    const int rowBase = blockIdx.x * 128;

    __shared__ float sA[2][16][128]; // [k][m]
    __shared__ float sB[2][16][128]; // [k][n]

    float best[8];
    int   bidx[8];
#pragma unroll
    for (int i = 0; i < 8; i++) { best[i] = 3.4e38f; bidx[i] = 0; }

    for (int nb = 0; nb < 8; nb++) {
        const int nBase = nb * 128;
        unsigned long long acc[8][4];
#pragma unroll
        for (int i = 0; i < 8; i++)
#pragma unroll
            for (int j = 0; j < 4; j++) acc[i][j] = 0ull;

        // load chunk 0
#pragma unroll
        for (int it = 0; it < 2; it++) {
            int id = tid + it * 256;
            int m = id >> 2, c4 = id & 3;
            float4 v = *(const float4*)&g_xb[(size_t)(rowBase + m) * DDIM + c4 * 4];
            sA[0][c4 * 4 + 0][m] = v.x; sA[0][c4 * 4 + 1][m] = v.y;
            sA[0][c4 * 4 + 2][m] = v.z; sA[0][c4 * 4 + 3][m] = v.w;
            int r = id >> 5, c32 = id & 31;
            float4 w = *(const float4*)&E[(size_t)r * KCODES + nBase + c32 * 4];
            *(float4*)&sB[0][r][c32 * 4] = w;
        }
        __syncthreads();

        int buf = 0;
        for (int kc = 0; kc < 16; kc++) {
            float4 rA[2], rB[2];
            if (kc < 15) {
#pragma unroll
                for (int it = 0; it < 2; it++) {
                    int id = tid + it * 256;
                    int m = id >> 2, c4 = id & 3;
                    rA[it] = *(const float4*)&g_xb[(size_t)(rowBase + m) * DDIM + (kc + 1) * 16 + c4 * 4];
                    int r = id >> 5, c32 = id & 31;
                    rB[it] = *(const float4*)&E[(size_t)((kc + 1) * 16 + r) * KCODES + nBase + c32 * 4];
                }
            }
#pragma unroll
            for (int k = 0; k < 16; k++) {
                float a[8];
                *(float4*)&a[0] = *(const float4*)&sA[buf][k][ty * 8];
                *(float4*)&a[4] = *(const float4*)&sA[buf][k][ty * 8 + 4];
                unsigned long long b[4];
                const double2* bp = (const double2*)&sB[buf][k][tx * 8];
                double2 b01 = bp[0], b23 = bp[1];
                b[0] = __double_as_longlong(b01.x); b[1] = __double_as_longlong(b01.y);
                b[2] = __double_as_longlong(b23.x); b[3] = __double_as_longlong(b23.y);
#pragma unroll
                for (int i = 0; i < 8; i++) {
                    unsigned long long ad;
                    unsigned int au = __float_as_uint(a[i]);
                    asm("mov.b64 %0, {%1, %1};" : "=l"(ad) : "r"(au));
#pragma unroll
                    for (int j = 0; j < 4; j++)
                        asm("fma.rn.f32x2 %0, %1, %2, %0;" : "+l"(acc[i][j]) : "l"(ad), "l"(b[j]));
                }
            }
            if (kc < 15) {
#pragma unroll
                for (int it = 0; it < 2; it++) {
                    int id = tid + it * 256;
                    int m = id >> 2, c4 = id & 3;
                    float4 v = rA[it];
                    sA[buf ^ 1][c4 * 4 + 0][m] = v.x; sA[buf ^ 1][c4 * 4 + 1][m] = v.y;
                    sA[buf ^ 1][c4 * 4 + 2][m] = v.z; sA[buf ^ 1][c4 * 4 + 3][m] = v.w;
                    int r = id >> 5, c32 = id & 31;
                    *(float4*)&sB[buf ^ 1][r][c32 * 4] = rB[it];
                }
            }
            __syncthreads();
            buf ^= 1;
        }

        // distances + running argmin (increasing index order => first-min tie rule)
#pragma unroll
        for (int i = 0; i < 8; i++) {
#pragma unroll
            for (int j = 0; j < 4; j++) {
                unsigned long long v = acc[i][j];
                float lo = __uint_as_float((unsigned)(v & 0xffffffffull));
                float hi = __uint_as_float((unsigned)(v >> 32));
                int n0 = nBase + tx * 8 + j * 2;
                float d0 = g_csq[n0]     - 2.f * lo;
                float d1 = g_csq[n0 + 1] - 2.f * hi;
                if (d0 < best[i]) { best[i] = d0; bidx[i] = n0; }
                if (d1 < best[i]) { best[i] = d1; bidx[i] = n0 + 1; }
            }
        }
    }

    // cross-thread reduction (reuse smem)
    float* sval = &sA[0][0][0];       // 2048 floats
    int*   sidx = (int*)&sB[0][0][0]; // 2048 ints
#pragma unroll
    for (int i = 0; i < 8; i++) {
        sval[(ty * 8 + i) * 16 + tx] = best[i];
        sidx[(ty * 8 + i) * 16 + tx] = bidx[i];
    }
    __syncthreads();
    if (tid < 128) {
        float bv = 3.4e38f; int bi = 1 << 30;
        for (int t = 0; t < 16; t++) {
            float v = sval[tid * 16 + t];
            int  ix = sidx[tid * 16 + t];
            if (v < bv || (v == bv && ix < bi)) { bv = v; bi = ix; }
        }
        g_idx[rowBase + tid] = bi;
    }
}

// ---------------- K7: gather q, quantized output, loss, counts, idx_out ------
__global__ void k_quant(const int* __restrict__ mask, float* __restrict__ outQ,
                        float* __restrict__ outIdx) {
    int w = threadIdx.x >> 5, lane = threadIdx.x & 31;
    int row = blockIdx.x * 8 + w;
    int m = mask[row];
    int idx = g_idx[row];
    const float4* qv = (const float4*)&g_ET[(size_t)idx * DDIM];
    const float4* xv = (const float4*)&g_xb[(size_t)row * DDIM];
    float4* ov = (float4*)&outQ[(size_t)row * DDIM];
    float ls = 0.f;
#pragma unroll
    for (int t = 0; t < 2; t++) {
        int j = lane + t * 32;
        float4 q = qv[j];
        if (m) {
            float4 xb = xv[j];
            float a = xb.x - q.x, b = xb.y - q.y, c = xb.z - q.z, e = xb.w - q.w;
            ls += a * a + b * b + c * c + e * e;
            ov[j] = q;
        } else {
            ov[j] = make_float4(0.f, 0.f, 0.f, 0.f);
        }
    }
    for (int o = 16; o; o >>= 1) ls += __shfl_down_sync(0xffffffffu, ls, o);
    __shared__ float red[8];
    if (lane == 0) {
        red[w] = m ? ls : 0.f;
        outIdx[row] = m ? (float)idx : -1.f;
        if (m) atomicAdd(&g_counts[idx], 1.f);
    }
    __syncthreads();
    if (threadIdx.x == 0) {
        float t = 0.f;
        for (int i = 0; i < 8; i++) t += red[i];
        atomicAdd(&g_loss, (double)t);
    }
}

// ---------------- K8: finalize scalars ---------------------------------------
__global__ void k_final(float* __restrict__ out) {
    int t = threadIdx.x;           // 1024 threads
    float nv = fmaxf(g_cnt, 1.f);
    float p = g_counts[t] / nv;
    float h = -p * logf(p + 1e-10f);
    for (int o = 16; o; o >>= 1) h += __shfl_down_sync(0xffffffffu, h, o);
    __shared__ float red[32];
    if ((t & 31) == 0) red[t >> 5] = h;
    __syncthreads();
    if (t < 32) {
        float s = red[t];
        for (int o = 16; o; o >>= 1) s += __shfl_down_sync(0xffffffffu, s, o);
        if (t == 0) {
            float loss = (float)(g_loss / ((double)nv * (double)DDIM));
            out[OFF_DICT]   = loss;
            out[OFF_COMMIT] = loss;
            out[OFF_PERP]   = expf(s);
        }
    }
}

// ---------------- launch ------------------------------------------------------
extern "C" void kernel_launch(void* const* d_in, const int* in_sizes, int n_in,
                              void* d_out, int out_size) {
    const float* x     = (const float*)d_in[0];
    const int*   mask  = (const int*)  d_in[1];
    const float* E     = (const float*)d_in[2];
    const float* gamma = (const float*)d_in[3];
    const float* beta  = (const float*)d_in[4];
    float* out = (float*)d_out;

    k_zero<<<4, 256>>>();
    k_stats<<<256, 256>>>(x, mask);
    k_reduce_stats<<<1, 256>>>(gamma, beta);
    k_norm<<<BNROWS, 256>>>(x);
    dim3 tg(32, 8), tb(32, 8);
    k_transpose<<<tg, tb>>>(E);
    k_csq<<<KCODES, 256>>>();
    k_argmin<<<BNROWS / 128, 256>>>(E);
    k_quant<<<BNROWS / 8, 256>>>(mask, out + OFF_Q, out + OFF_IDX);
    k_final<<<1, 1024>>>(out);
}

// round 3
// speedup vs baseline: 2.1155x; 2.1155x over previous
#include <cuda_runtime.h>
#include <cuda_fp16.h>
#include <cstdint>
#include <math.h>

// Problem dims
#define BNROWS 32768   // B*N
#define DDIM   256
#define KCODES 1024
#define KEFF   768     // 3 fp16 passes fused as one K

// Output layout (float32, reference return order)
#define OFF_Q      0ull
#define OFF_DICT   8388608ull
#define OFF_COMMIT 8388609ull
#define OFF_IDX    8388610ull
#define OFF_PERP   8421378ull

// ---------------- scratch (device globals) -----------------------------------
__device__ float  g_partS [256][DDIM];
__device__ float  g_partS2[256][DDIM];
__device__ float  g_partC [256];
__device__ float  g_cnt;
__device__ __align__(16) float g_scale[DDIM];
__device__ __align__(16) float g_shift[DDIM];
__device__ __align__(16) __half g_xA[(size_t)BNROWS * KEFF]; // [x_h | x_h | x_l]
__device__ __align__(16) __half g_eB[(size_t)KCODES * KEFF]; // [e_h | e_l | e_h]
__device__ __align__(16) float g_ET[(size_t)KCODES * DDIM];  // codebook^T [K][D]
__device__ __align__(16) float g_csq[KCODES];
__device__ int    g_idx[BNROWS];
__device__ float  g_counts[KCODES];
__device__ double g_loss;

// ---------------- helpers ------------------------------------------------------
__device__ __forceinline__ uint32_t s2u(const void* p) {
    uint32_t a;
    asm("{ .reg .u64 t; cvta.to.shared.u64 t, %1; cvt.u32.u64 %0, t; }" : "=r"(a) : "l"(p));
    return a;
}
__device__ __forceinline__ uint32_t swz(uint32_t off) { return off ^ ((off >> 3) & 0x70); }

__device__ __forceinline__ void cp16(uint32_t dst, const void* src) {
    asm volatile("cp.async.cg.shared.global [%0], [%1], 16;" :: "r"(dst), "l"(src) : "memory");
}
#define CP_COMMIT() asm volatile("cp.async.commit_group;" ::: "memory")

__device__ __forceinline__ void ldsm_x4(uint32_t* r, uint32_t addr) {
    asm volatile("ldmatrix.sync.aligned.m8n8.x4.shared.b16 {%0,%1,%2,%3}, [%4];"
                 : "=r"(r[0]), "=r"(r[1]), "=r"(r[2]), "=r"(r[3]) : "r"(addr));
}
__device__ __forceinline__ void ldsm_x2(uint32_t* r, uint32_t addr) {
    asm volatile("ldmatrix.sync.aligned.m8n8.x2.shared.b16 {%0,%1}, [%2];"
                 : "=r"(r[0]), "=r"(r[1]) : "r"(addr));
}
__device__ __forceinline__ void mma16816(float* c, const uint32_t* a, const uint32_t* b) {
    asm volatile(
        "mma.sync.aligned.m16n8k16.row.col.f32.f16.f16.f32 "
        "{%0,%1,%2,%3}, {%4,%5,%6,%7}, {%8,%9}, {%0,%1,%2,%3};"
        : "+f"(c[0]), "+f"(c[1]), "+f"(c[2]), "+f"(c[3])
        : "r"(a[0]), "r"(a[1]), "r"(a[2]), "r"(a[3]), "r"(b[0]), "r"(b[1]));
}

// ---------------- K0: zero accumulators ----------------------------------------
__global__ void k_zero() {
    int i = blockIdx.x * 256 + threadIdx.x;
    if (i < KCODES) g_counts[i] = 0.f;
    if (i == 0) g_loss = 0.0;
}

// ---------------- K1: masked per-column partial sums ----------------------------
__global__ void k_stats(const float* __restrict__ x, const int* __restrict__ mask) {
    int d4 = threadIdx.x;   // 0..63 (float4 columns)
    int ty = threadIdx.y;   // 0..3
    int b  = blockIdx.x;
    int r0 = b * 128 + ty * 32;
    const float4* x4 = (const float4*)x;
    float4 s  = make_float4(0.f, 0.f, 0.f, 0.f);
    float4 s2 = make_float4(0.f, 0.f, 0.f, 0.f);
    float  c  = 0.f;
    for (int r = 0; r < 32; r++) {
        if (mask[r0 + r]) {
            float4 v = x4[(size_t)(r0 + r) * 64 + d4];
            s.x += v.x; s.y += v.y; s.z += v.z; s.w += v.w;
            s2.x += v.x * v.x; s2.y += v.y * v.y; s2.z += v.z * v.z; s2.w += v.w * v.w;
            c += 1.f;
        }
    }
    __shared__ float4 sS[4][64], sS2[4][64];
    __shared__ float  sC[4];
    sS[ty][d4] = s; sS2[ty][d4] = s2;
    if (d4 == 0) sC[ty] = c;
    __syncthreads();
    if (ty == 0) {
        for (int y = 1; y < 4; y++) {
            float4 a = sS[y][d4], a2 = sS2[y][d4];
            s.x += a.x; s.y += a.y; s.z += a.z; s.w += a.w;
            s2.x += a2.x; s2.y += a2.y; s2.z += a2.z; s2.w += a2.w;
        }
        ((float4*)g_partS [b])[d4] = s;
        ((float4*)g_partS2[b])[d4] = s2;
        if (d4 == 0) g_partC[b] = sC[0] + sC[1] + sC[2] + sC[3];
    }
}

// ---------------- K2: reduce stats -> scale/shift --------------------------------
__global__ void k_reduce_stats(const float* __restrict__ gamma, const float* __restrict__ beta) {
    int d = threadIdx.x;
    float s = 0.f, s2 = 0.f, cnt = 0.f;
    for (int b = 0; b < 256; b++) {
        s  += g_partS [b][d];
        s2 += g_partS2[b][d];
        cnt += g_partC[b];
    }
    if (d == 0) g_cnt = cnt;
    float nv = fmaxf(cnt, 1.f);
    float mu  = s / nv;
    float var = s2 / nv - mu * mu;
    float sc  = rsqrtf(var + 1e-5f) * gamma[d];
    g_scale[d] = sc;
    g_shift[d] = beta[d] - mu * sc;
}

// ---------------- K3: xb -> fp16 split, packed A [x_h | x_h | x_l] ---------------
__global__ void k_splitx(const float* __restrict__ x) {
    int i = blockIdx.x * 256 + threadIdx.x;    // float4 index
    int row = i >> 6, c4 = i & 63;
    float4 xv = ((const float4*)x)[i];
    float4 sc = ((const float4*)g_scale)[c4];
    float4 sh = ((const float4*)g_shift)[c4];
    float b0 = xv.x * sc.x + sh.x;
    float b1 = xv.y * sc.y + sh.y;
    float b2 = xv.z * sc.z + sh.z;
    float b3 = xv.w * sc.w + sh.w;
    __half2 h01 = __floats2half2_rn(b0, b1);
    __half2 h23 = __floats2half2_rn(b2, b3);
    __half2 l01 = __floats2half2_rn(b0 - __low2float(h01), b1 - __high2float(h01));
    __half2 l23 = __floats2half2_rn(b2 - __low2float(h23), b3 - __high2float(h23));
    __half2* dst = (__half2*)&g_xA[(size_t)row * KEFF];
    dst[c4 * 2]           = h01; dst[c4 * 2 + 1]       = h23;
    dst[128 + c4 * 2]     = h01; dst[128 + c4 * 2 + 1] = h23;
    dst[256 + c4 * 2]     = l01; dst[256 + c4 * 2 + 1] = l23;
}

// ---------------- K4: transpose E [D][K] -> ET [K][D] -----------------------------
__global__ void k_transpose(const float* __restrict__ E) {
    __shared__ float t[32][33];
    int x0 = blockIdx.x * 32;  // code
    int y0 = blockIdx.y * 32;  // d
    for (int j = threadIdx.y; j < 32; j += 8)
        t[j][threadIdx.x] = E[(size_t)(y0 + j) * KCODES + x0 + threadIdx.x];
    __syncthreads();
    for (int j = threadIdx.y; j < 32; j += 8)
        g_ET[(size_t)(x0 + j) * DDIM + y0 + threadIdx.x] = t[threadIdx.x][j];
}

// ---------------- K5: code squared norms -------------------------------------------
__global__ void k_csq() {
    int c = blockIdx.x;
    float v = g_ET[(size_t)c * DDIM + threadIdx.x];
    float s = v * v;
    for (int o = 16; o; o >>= 1) s += __shfl_down_sync(0xffffffffu, s, o);
    __shared__ float red[8];
    if ((threadIdx.x & 31) == 0) red[threadIdx.x >> 5] = s;
    __syncthreads();
    if (threadIdx.x < 8) {
        float t = red[threadIdx.x];
        for (int o = 4; o; o >>= 1) t += __shfl_down_sync(0xffu, t, o);
        if (threadIdx.x == 0) g_csq[c] = t;
    }
}

// ---------------- K5b: codes -> fp16 split, packed B [e_h | e_l | e_h] --------------
__global__ void k_splite() {
    int i = blockIdx.x * 256 + threadIdx.x;   // float4 index over ET
    int row = i >> 6, c4 = i & 63;
    float4 v = ((const float4*)g_ET)[i];
    __half2 h01 = __floats2half2_rn(v.x, v.y);
    __half2 h23 = __floats2half2_rn(v.z, v.w);
    __half2 l01 = __floats2half2_rn(v.x - __low2float(h01), v.y - __high2float(h01));
    __half2 l23 = __floats2half2_rn(v.z - __low2float(h23), v.w - __high2float(h23));
    __half2* dst = (__half2*)&g_eB[(size_t)row * KEFF];
    dst[c4 * 2]           = h01; dst[c4 * 2 + 1]       = h23;
    dst[128 + c4 * 2]     = l01; dst[128 + c4 * 2 + 1] = l23;
    dst[256 + c4 * 2]     = h01; dst[256 + c4 * 2 + 1] = h23;
}

// ---------------- K6: HMMA GEMM (K=768) + argmin -------------------------------------
// Per CTA: 128 rows x 1024 codes. A resident in smem (12 chunks of 128x128B),
// B streamed (96 chunks of 128x128B, 2 buffers, cp.async). 8 warps = 2(m) x 4(n),
// warp tile 64x32, mma.sync m16n8k16 fp16->fp32.
#define A_BYTES  196608              // 12 * 16384
#define B_BYTES  32768               // 2 * 16384
#define SMEMSZ   (A_BYTES + B_BYTES)
#define NCHUNK   96                  // 8 n-tiles * 12 k-chunks

__global__ void __launch_bounds__(256) k_mma_argmin() {
    extern __shared__ char smem[];
    const uint32_t sbA = s2u(smem);
    const uint32_t sbB = sbA + A_BYTES;
    const int tid  = threadIdx.x;
    const int lane = tid & 31;
    const int wid  = tid >> 5;
    const int wm   = wid >> 2;       // 0..1
    const int wn   = wid & 3;        // 0..3
    const int rowBase = blockIdx.x * 128;

    // ---- prologue: A resident load (one commit group) ----
    {
        const char* asrc = (const char*)g_xA + (size_t)rowBase * KEFF * 2;
#pragma unroll
        for (int v = 0; v < 48; v++) {
            int idx = tid + v * 256;          // 0..12287 (16B units)
            int ch = idx >> 10, rem = idx & 1023;
            int r = rem >> 3, j = rem & 7;
            uint32_t dst = sbA + (ch << 14) + swz((r << 7) + (j << 4));
            cp16(dst, asrc + ((size_t)r * KEFF + ch * 64 + j * 8) * 2);
        }
        CP_COMMIT();
    }
    // ---- B chunks 0,1 ----
#pragma unroll
    for (int c0 = 0; c0 < 2; c0++) {
        const char* bsrc = (const char*)g_eB + (size_t)(c0 * 64) * 2; // nb=0
#pragma unroll
        for (int v = 0; v < 4; v++) {
            int idx = tid + v * 256;
            int r = idx >> 3, j = idx & 7;
            uint32_t dst = sbB + (c0 << 14) + swz((r << 7) + (j << 4));
            cp16(dst, bsrc + ((size_t)r * KEFF + j * 8) * 2);
        }
        CP_COMMIT();
    }

    float acc[4][4][4];
    float best[8];
    int   bidx[8];
#pragma unroll
    for (int s = 0; s < 8; s++) { best[s] = 3.4e38f; bidx[s] = 0; }

    // fragment smem address bases (lane-dependent parts)
    const uint32_t aRow = (uint32_t)(wm * 64 + (lane & 15));
    const uint32_t aKG  = (uint32_t)((lane >> 4) << 4);
    const uint32_t bRow = (uint32_t)(wn * 32 + (lane & 7));
    const uint32_t bKG  = (uint32_t)(((lane >> 3) & 1) << 4);

#pragma unroll 1
    for (int c = 0; c < NCHUNK; c++) {
        const int kc = c % 12;
        const int nb = c / 12;
        const int buf = c & 1;

        if (c == NCHUNK - 1) asm volatile("cp.async.wait_group 0;" ::: "memory");
        else                 asm volatile("cp.async.wait_group 1;" ::: "memory");
        __syncthreads();

        if (kc == 0) {
#pragma unroll
            for (int mf = 0; mf < 4; mf++)
#pragma unroll
                for (int nf = 0; nf < 4; nf++)
#pragma unroll
                    for (int t = 0; t < 4; t++) acc[mf][nf][t] = 0.f;
        }

#pragma unroll
        for (int ks = 0; ks < 4; ks++) {
            uint32_t a[4][4], b[4][2];
#pragma unroll
            for (int mf = 0; mf < 4; mf++)
                ldsm_x4(a[mf], sbA + (kc << 14) +
                        swz(((aRow + mf * 16) << 7) + ks * 32 + aKG));
#pragma unroll
            for (int nf = 0; nf < 4; nf++)
                ldsm_x2(b[nf], sbB + (buf << 14) +
                        swz(((bRow + nf * 8) << 7) + ks * 32 + bKG));
#pragma unroll
            for (int mf = 0; mf < 4; mf++)
#pragma unroll
                for (int nf = 0; nf < 4; nf++)
                    mma16816(acc[mf][nf], a[mf], b[nf]);
        }

        if (kc == 11) {
            // epilogue for n-tile nb: distances + running argmin
            const float* csqp = g_csq + nb * 128 + wn * 32 + 2 * (lane & 3);
#pragma unroll
            for (int nf = 0; nf < 4; nf++) {
                float q0 = __ldg(csqp + nf * 8);
                float q1 = __ldg(csqp + nf * 8 + 1);
                int n0 = nb * 128 + wn * 32 + nf * 8 + 2 * (lane & 3);
#pragma unroll
                for (int mf = 0; mf < 4; mf++) {
                    float d0 = q0 - 2.f * acc[mf][nf][0];
                    float d1 = q1 - 2.f * acc[mf][nf][1];
                    float d2 = q0 - 2.f * acc[mf][nf][2];
                    float d3 = q1 - 2.f * acc[mf][nf][3];
                    int s0 = mf * 2, s1 = mf * 2 + 1;
                    if (d0 < best[s0]) { best[s0] = d0; bidx[s0] = n0; }
                    if (d1 < best[s0]) { best[s0] = d1; bidx[s0] = n0 + 1; }
                    if (d2 < best[s1]) { best[s1] = d2; bidx[s1] = n0; }
                    if (d3 < best[s1]) { best[s1] = d3; bidx[s1] = n0 + 1; }
                }
            }
        }
        __syncthreads();

        if (c + 2 < NCHUNK) {
            const int cc = c + 2, nb2 = cc / 12, kc2 = cc % 12;
            const char* bsrc = (const char*)g_eB +
                               ((size_t)(nb2 * 128) * KEFF + kc2 * 64) * 2;
#pragma unroll
            for (int v = 0; v < 4; v++) {
                int idx = tid + v * 256;
                int r = idx >> 3, j = idx & 7;
                uint32_t dst = sbB + (buf << 14) + swz((r << 7) + (j << 4));
                cp16(dst, bsrc + ((size_t)r * KEFF + j * 8) * 2);
            }
            CP_COMMIT();
        }
    }

    // ---- final argmin reduction (reuse A smem region) ----
    __syncthreads();
    float* rv = (float*)smem;               // [128][4]
    int*   ri = (int*)(smem + 2048);        // [128][4]
#pragma unroll
    for (int s = 0; s < 8; s++) {
        float v = best[s];
        int   ix = bidx[s];
#pragma unroll
        for (int off = 1; off <= 2; off <<= 1) {
            float ov = __shfl_xor_sync(0xffffffffu, v, off);
            int   oi = __shfl_xor_sync(0xffffffffu, ix, off);
            if (ov < v || (ov == v && oi < ix)) { v = ov; ix = oi; }
        }
        if ((lane & 3) == 0) {
            int row = wm * 64 + (s >> 1) * 16 + (lane >> 2) + (s & 1) * 8;
            rv[row * 4 + wn] = v;
            ri[row * 4 + wn] = ix;
        }
    }
    __syncthreads();
    if (tid < 128) {
        float bv = rv[tid * 4];
        int   bi = ri[tid * 4];
        for (int t = 1; t < 4; t++) {
            float v = rv[tid * 4 + t];
            int   i = ri[tid * 4 + t];
            if (v < bv || (v == bv && i < bi)) { bv = v; bi = i; }
        }
        g_idx[rowBase + tid] = bi;
    }
}

// ---------------- K7: gather q, output, loss, counts, idx ----------------------------
__global__ void k_quant(const float* __restrict__ x, const int* __restrict__ mask,
                        float* __restrict__ outQ, float* __restrict__ outIdx) {
    int w = threadIdx.x >> 5, lane = threadIdx.x & 31;
    int row = blockIdx.x * 8 + w;
    int m = mask[row];
    int idx = g_idx[row];
    const float4* qv  = (const float4*)&g_ET[(size_t)idx * DDIM];
    const float4* xv  = (const float4*)&x[(size_t)row * DDIM];
    const float4* scv = (const float4*)g_scale;
    const float4* shv = (const float4*)g_shift;
    float4* ov = (float4*)&outQ[(size_t)row * DDIM];
    float ls = 0.f;
#pragma unroll
    for (int t = 0; t < 2; t++) {
        int j = lane + t * 32;
        float4 q = qv[j];
        if (m) {
            float4 xr = xv[j], sc = scv[j], sh = shv[j];
            float a = xr.x * sc.x + sh.x - q.x;
            float b = xr.y * sc.y + sh.y - q.y;
            float c = xr.z * sc.z + sh.z - q.z;
            float e = xr.w * sc.w + sh.w - q.w;
            ls += a * a + b * b + c * c + e * e;
            ov[j] = q;
        } else {
            ov[j] = make_float4(0.f, 0.f, 0.f, 0.f);
        }
    }
    for (int o = 16; o; o >>= 1) ls += __shfl_down_sync(0xffffffffu, ls, o);
    __shared__ float red[8];
    if (lane == 0) {
        red[w] = m ? ls : 0.f;
        outIdx[row] = m ? (float)idx : -1.f;
        if (m) atomicAdd(&g_counts[idx], 1.f);
    }
    __syncthreads();
    if (threadIdx.x == 0) {
        float t = 0.f;
        for (int i = 0; i < 8; i++) t += red[i];
        atomicAdd(&g_loss, (double)t);
    }
}

// ---------------- K8: finalize scalars -------------------------------------------------
__global__ void k_final(float* __restrict__ out) {
    int t = threadIdx.x;  // 1024 threads
    float nv = fmaxf(g_cnt, 1.f);
    float p = g_counts[t] / nv;
    float h = -p * logf(p + 1e-10f);
    for (int o = 16; o; o >>= 1) h += __shfl_down_sync(0xffffffffu, h, o);
    __shared__ float red[32];
    if ((t & 31) == 0) red[t >> 5] = h;
    __syncthreads();
    if (t < 32) {
        float s = red[t];
        for (int o = 16; o; o >>= 1) s += __shfl_down_sync(0xffffffffu, s, o);
        if (t == 0) {
            float loss = (float)(g_loss / ((double)nv * (double)DDIM));
            out[OFF_DICT]   = loss;
            out[OFF_COMMIT] = loss;
            out[OFF_PERP]   = expf(s);
        }
    }
}

// ---------------- launch ----------------------------------------------------------------
extern "C" void kernel_launch(void* const* d_in, const int* in_sizes, int n_in,
                              void* d_out, int out_size) {
    const float* x     = (const float*)d_in[0];
    const int*   mask  = (const int*)  d_in[1];
    const float* E     = (const float*)d_in[2];
    const float* gamma = (const float*)d_in[3];
    const float* beta  = (const float*)d_in[4];
    float* out = (float*)d_out;

    cudaFuncSetAttribute(k_mma_argmin, cudaFuncAttributeMaxDynamicSharedMemorySize, SMEMSZ);

    k_zero<<<4, 256>>>();
    k_stats<<<256, dim3(64, 4)>>>(x, mask);
    k_reduce_stats<<<1, 256>>>(gamma, beta);
    k_splitx<<<BNROWS * 64 / 256, 256>>>(x);
    dim3 tg(32, 8), tb(32, 8);
    k_transpose<<<tg, tb>>>(E);
    k_csq<<<KCODES, 256>>>();
    k_splite<<<KCODES * 64 / 256, 256>>>();
    k_mma_argmin<<<BNROWS / 128, 256, SMEMSZ>>>();
    k_quant<<<BNROWS / 8, 256>>>(x, mask, out + OFF_Q, out + OFF_IDX);
    k_final<<<1, 1024>>>(out);
}

// round 4
// speedup vs baseline: 2.3512x; 1.1114x over previous
#include <cuda_runtime.h>
#include <cuda_fp16.h>
#include <cstdint>
#include <math.h>

// Problem dims
#define BNROWS 32768   // B*N
#define DDIM   256
#define KCODES 1024

// Output layout (float32, reference return order)
#define OFF_Q      0ull
#define OFF_DICT   8388608ull
#define OFF_COMMIT 8388609ull
#define OFF_IDX    8388610ull
#define OFF_PERP   8421378ull

// ---------------- scratch (device globals) -----------------------------------
__device__ float  g_partS [256][DDIM];
__device__ float  g_partS2[256][DDIM];
__device__ float  g_partC [256];
__device__ float  g_cnt;
__device__ __align__(16) float g_scale[DDIM];
__device__ __align__(16) float g_shift[DDIM];
__device__ __align__(16) __half g_xh[(size_t)BNROWS * DDIM];
__device__ __align__(16) __half g_xl[(size_t)BNROWS * DDIM];
__device__ __align__(16) __half g_eB2[(size_t)KCODES * 512]; // [e_h(256) | e_l(256)]
__device__ __align__(16) float g_ET[(size_t)KCODES * DDIM];  // codebook^T [K][D]
__device__ __align__(16) float g_csq[KCODES];
__device__ float  g_xsq[BNROWS];
__device__ float  g_best[BNROWS];
__device__ int    g_idx[BNROWS];
__device__ float  g_counts[KCODES];
__device__ double g_loss;

// ---------------- helpers ------------------------------------------------------
__device__ __forceinline__ uint32_t s2u(const void* p) {
    uint32_t a;
    asm("{ .reg .u64 t; cvta.to.shared.u64 t, %1; cvt.u32.u64 %0, t; }" : "=r"(a) : "l"(p));
    return a;
}
__device__ __forceinline__ uint32_t swz(uint32_t off) { return off ^ ((off >> 3) & 0x70); }

__device__ __forceinline__ void cp16(uint32_t dst, const void* src) {
    asm volatile("cp.async.cg.shared.global [%0], [%1], 16;" :: "r"(dst), "l"(src) : "memory");
}
#define CP_COMMIT() asm volatile("cp.async.commit_group;" ::: "memory")

__device__ __forceinline__ void ldsm_x4(uint32_t* r, uint32_t addr) {
    asm volatile("ldmatrix.sync.aligned.m8n8.x4.shared.b16 {%0,%1,%2,%3}, [%4];"
                 : "=r"(r[0]), "=r"(r[1]), "=r"(r[2]), "=r"(r[3]) : "r"(addr));
}
__device__ __forceinline__ void ldsm_x2(uint32_t* r, uint32_t addr) {
    asm volatile("ldmatrix.sync.aligned.m8n8.x2.shared.b16 {%0,%1}, [%2];"
                 : "=r"(r[0]), "=r"(r[1]) : "r"(addr));
}
__device__ __forceinline__ void mma16816(float* c, const uint32_t* a, const uint32_t* b) {
    asm volatile(
        "mma.sync.aligned.m16n8k16.row.col.f32.f16.f16.f32 "
        "{%0,%1,%2,%3}, {%4,%5,%6,%7}, {%8,%9}, {%0,%1,%2,%3};"
        : "+f"(c[0]), "+f"(c[1]), "+f"(c[2]), "+f"(c[3])
        : "r"(a[0]), "r"(a[1]), "r"(a[2]), "r"(a[3]), "r"(b[0]), "r"(b[1]));
}

// ---------------- K1: zero accumulators ----------------------------------------
__global__ void k_zero() {
    int i = blockIdx.x * 256 + threadIdx.x;
    if (i < KCODES) { g_counts[i] = 0.f; g_csq[i] = 0.f; }
    if (i == 0) g_loss = 0.0;
}

// ---------------- K2: masked per-column partial sums ----------------------------
__global__ void k_stats(const float* __restrict__ x, const int* __restrict__ mask) {
    int d4 = threadIdx.x;   // 0..63 (float4 columns)
    int ty = threadIdx.y;   // 0..3
    int b  = blockIdx.x;
    int r0 = b * 128 + ty * 32;
    const float4* x4 = (const float4*)x;
    float4 s  = make_float4(0.f, 0.f, 0.f, 0.f);
    float4 s2 = make_float4(0.f, 0.f, 0.f, 0.f);
    float  c  = 0.f;
    for (int r = 0; r < 32; r++) {
        if (mask[r0 + r]) {
            float4 v = x4[(size_t)(r0 + r) * 64 + d4];
            s.x += v.x; s.y += v.y; s.z += v.z; s.w += v.w;
            s2.x += v.x * v.x; s2.y += v.y * v.y; s2.z += v.z * v.z; s2.w += v.w * v.w;
            c += 1.f;
        }
    }
    __shared__ float4 sS[4][64], sS2[4][64];
    __shared__ float  sC[4];
    sS[ty][d4] = s; sS2[ty][d4] = s2;
    if (d4 == 0) sC[ty] = c;
    __syncthreads();
    if (ty == 0) {
        for (int y = 1; y < 4; y++) {
            float4 a = sS[y][d4], a2 = sS2[y][d4];
            s.x += a.x; s.y += a.y; s.z += a.z; s.w += a.w;
            s2.x += a2.x; s2.y += a2.y; s2.z += a2.z; s2.w += a2.w;
        }
        ((float4*)g_partS [b])[d4] = s;
        ((float4*)g_partS2[b])[d4] = s2;
        if (d4 == 0) g_partC[b] = sC[0] + sC[1] + sC[2] + sC[3];
    }
}

// ---------------- K3: reduce stats -> scale/shift --------------------------------
__global__ void k_reduce_stats(const float* __restrict__ gamma, const float* __restrict__ beta) {
    int d = threadIdx.x;
    float s = 0.f, s2 = 0.f, cnt = 0.f;
#pragma unroll 8
    for (int b = 0; b < 256; b++) {
        s  += g_partS [b][d];
        s2 += g_partS2[b][d];
        cnt += g_partC[b];
    }
    if (d == 0) g_cnt = cnt;
    float nv = fmaxf(cnt, 1.f);
    float mu  = s / nv;
    float var = s2 / nv - mu * mu;
    float sc  = rsqrtf(var + 1e-5f) * gamma[d];
    g_scale[d] = sc;
    g_shift[d] = beta[d] - mu * sc;
}

// ---------------- K4: xb -> fp16 split (xh, xl) + per-row ||xb||^2 ---------------
__global__ void k_splitx(const float* __restrict__ x) {
    int tid = threadIdx.x;
    int i = blockIdx.x * 256 + tid;   // float4 index; 4 rows per block
    int row = i >> 6, c4 = i & 63;
    float4 xv = ((const float4*)x)[i];
    float4 sc = ((const float4*)g_scale)[c4];
    float4 sh = ((const float4*)g_shift)[c4];
    float b0 = xv.x * sc.x + sh.x;
    float b1 = xv.y * sc.y + sh.y;
    float b2 = xv.z * sc.z + sh.z;
    float b3 = xv.w * sc.w + sh.w;
    __half2 h01 = __floats2half2_rn(b0, b1);
    __half2 h23 = __floats2half2_rn(b2, b3);
    __half2 l01 = __floats2half2_rn(b0 - __low2float(h01), b1 - __high2float(h01));
    __half2 l23 = __floats2half2_rn(b2 - __low2float(h23), b3 - __high2float(h23));
    __half2* dh = (__half2*)&g_xh[(size_t)row * DDIM];
    __half2* dl = (__half2*)&g_xl[(size_t)row * DDIM];
    dh[c4 * 2] = h01; dh[c4 * 2 + 1] = h23;
    dl[c4 * 2] = l01; dl[c4 * 2 + 1] = l23;
    float s = b0 * b0 + b1 * b1 + b2 * b2 + b3 * b3;
    for (int o = 16; o; o >>= 1) s += __shfl_down_sync(0xffffffffu, s, o);
    __shared__ float red[8];
    if ((tid & 31) == 0) red[tid >> 5] = s;
    __syncthreads();
    if ((tid & 63) == 0) g_xsq[row] = red[tid >> 5] + red[(tid >> 5) + 1];
}

// ---------------- K5: transpose E + fp16 split + csq partials --------------------
__global__ void k_prep_e(const float* __restrict__ E) {
    __shared__ float t[32][33];
    int tx = threadIdx.x, ty = threadIdx.y;
    int x0 = blockIdx.x * 32;  // code
    int y0 = blockIdx.y * 32;  // d
    for (int j = ty; j < 32; j += 8)
        t[j][tx] = E[(size_t)(y0 + j) * KCODES + x0 + tx];
    __syncthreads();
    for (int j = ty; j < 32; j += 8) {
        int code = x0 + j, d = y0 + tx;
        float v = t[tx][j];
        g_ET[(size_t)code * DDIM + d] = v;
        __half h = __float2half_rn(v);
        g_eB2[(size_t)code * 512 + d]       = h;
        g_eB2[(size_t)code * 512 + 256 + d] = __float2half_rn(v - __half2float(h));
        float sq = v * v;
        for (int o = 16; o; o >>= 1) sq += __shfl_down_sync(0xffffffffu, sq, o);
        if (tx == 0) atomicAdd(&g_csq[code], sq);
    }
}

// ---------------- K6: HMMA GEMM + argmin (multistage, operand reuse) -------------
// Per CTA: 128 rows x 1024 codes. A resident (xh 4 + xl 4 chunks, 128KB).
// B: 8 chunks per n-tile (eh 4, el 4), 5-stage cp.async ring, one sync/chunk.
// eh chunks drive two MMA passes (xh, xl) reusing the same B fragments.
#define NSTG   5
#define B_OFF  131072
#define CSQ_OFF (131072 + NSTG * 16384)       // 212992
#define SMEMSZ  (CSQ_OFF + 4096)              // 217088
#define NCHUNK 64                             // 8 n-tiles * 8 chunks

__global__ void __launch_bounds__(256) k_mma_argmin() {
    extern __shared__ char smem[];
    const uint32_t sbA = s2u(smem);
    const uint32_t sbB = sbA + B_OFF;
    const int tid  = threadIdx.x;
    const int lane = tid & 31;
    const int wid  = tid >> 5;
    const int wm   = wid >> 2;       // 0..1
    const int wn   = wid & 3;        // 0..3
    const int rowBase = blockIdx.x * 128;

    // csq -> smem
    ((float4*)(smem + CSQ_OFF))[tid] = ((const float4*)g_csq)[tid];

    // ---- A resident load: 8 chunks (xh 0-3, xl 0-3), group 0 ----
    {
        const char* xh = (const char*)(g_xh + (size_t)rowBase * DDIM);
        const char* xl = (const char*)(g_xl + (size_t)rowBase * DDIM);
#pragma unroll
        for (int v = 0; v < 32; v++) {
            int idx = tid + v * 256;          // 0..8191 (16B units)
            int hs  = idx >> 12;              // 0=xh, 1=xl
            int rem = idx & 4095;
            int kk = rem >> 10, r = (rem >> 3) & 127, j = rem & 7;
            const char* src = (hs ? xl : xh) + ((size_t)r * DDIM + kk * 64 + j * 8) * 2;
            cp16(sbA + hs * 65536 + kk * 16384 + swz((r << 7) + (j << 4)), src);
        }
        CP_COMMIT();
    }
    // ---- B prologue: chunks 0..3 into stages 0..3 ----
#pragma unroll
    for (int c0 = 0; c0 < 4; c0++) {
        // nb=0, sl=c0
        const char* bs = (const char*)g_eB2;
#pragma unroll
        for (int v = 0; v < 4; v++) {
            int idx = tid + v * 256;
            int r = idx >> 3, j = idx & 7;
            cp16(sbB + c0 * 16384 + swz((r << 7) + (j << 4)),
                 bs + ((size_t)r * 512 + c0 * 64 + j * 8) * 2);
        }
        CP_COMMIT();
    }

    float acc[4][4][4];
    float best[8];
    int   bidx[8];
#pragma unroll
    for (int s = 0; s < 8; s++) { best[s] = 3.4e38f; bidx[s] = 0; }

    const uint32_t aRow = (uint32_t)(wm * 64 + (lane & 15));
    const uint32_t aKG  = (uint32_t)((lane >> 4) << 4);
    const uint32_t bRow = (uint32_t)(wn * 32 + (lane & 7));
    const uint32_t bKG  = (uint32_t)(((lane >> 3) & 1) << 4);
    const float* scsq = (const float*)(smem + CSQ_OFF);

    int stage = 0;
#pragma unroll 1
    for (int c = 0; c < NCHUNK; c++) {
        const int nb = c >> 3;
        const int sl = c & 7;
        const int kk = sl & 3;
        const bool dual = (sl < 4);   // eh chunk: drive xh and xl passes

        if (c >= NCHUNK - 4) asm volatile("cp.async.wait_group 0;" ::: "memory");
        else                 asm volatile("cp.async.wait_group 3;" ::: "memory");
        __syncthreads();

        if (sl == 0) {
#pragma unroll
            for (int mf = 0; mf < 4; mf++)
#pragma unroll
                for (int nf = 0; nf < 4; nf++)
#pragma unroll
                    for (int t = 0; t < 4; t++) acc[mf][nf][t] = 0.f;
        }

        const uint32_t bbase = sbB + stage * 16384;
        const uint32_t ah = sbA + kk * 16384;
        const uint32_t al = ah + 65536;
#pragma unroll
        for (int ks = 0; ks < 4; ks++) {
            uint32_t b[4][2];
#pragma unroll
            for (int nf = 0; nf < 4; nf++)
                ldsm_x2(b[nf], bbase + swz(((bRow + nf * 8) << 7) + ks * 32 + bKG));
            uint32_t a[4][4];
#pragma unroll
            for (int mf = 0; mf < 4; mf++)
                ldsm_x4(a[mf], ah + swz(((aRow + mf * 16) << 7) + ks * 32 + aKG));
#pragma unroll
            for (int mf = 0; mf < 4; mf++)
#pragma unroll
                for (int nf = 0; nf < 4; nf++)
                    mma16816(acc[mf][nf], a[mf], b[nf]);
            if (dual) {
                uint32_t a2[4][4];
#pragma unroll
                for (int mf = 0; mf < 4; mf++)
                    ldsm_x4(a2[mf], al + swz(((aRow + mf * 16) << 7) + ks * 32 + aKG));
#pragma unroll
                for (int mf = 0; mf < 4; mf++)
#pragma unroll
                    for (int nf = 0; nf < 4; nf++)
                        mma16816(acc[mf][nf], a2[mf], b[nf]);
            }
        }

        if (sl == 7) {
            // epilogue for n-tile nb: distances + running argmin
            const float* csqp = scsq + nb * 128 + wn * 32 + 2 * (lane & 3);
#pragma unroll
            for (int nf = 0; nf < 4; nf++) {
                float q0 = csqp[nf * 8];
                float q1 = csqp[nf * 8 + 1];
                int n0 = nb * 128 + wn * 32 + nf * 8 + 2 * (lane & 3);
#pragma unroll
                for (int mf = 0; mf < 4; mf++) {
                    float d0 = q0 - 2.f * acc[mf][nf][0];
                    float d1 = q1 - 2.f * acc[mf][nf][1];
                    float d2 = q0 - 2.f * acc[mf][nf][2];
                    float d3 = q1 - 2.f * acc[mf][nf][3];
                    int s0 = mf * 2, s1 = mf * 2 + 1;
                    if (d0 < best[s0]) { best[s0] = d0; bidx[s0] = n0; }
                    if (d1 < best[s0]) { best[s0] = d1; bidx[s0] = n0 + 1; }
                    if (d2 < best[s1]) { best[s1] = d2; bidx[s1] = n0; }
                    if (d3 < best[s1]) { best[s1] = d3; bidx[s1] = n0 + 1; }
                }
            }
        }

        if (c + 4 < NCHUNK) {
            const int cc = c + 4;
            const int nb2 = cc >> 3, sl2 = cc & 7;
            const int st2 = (stage + 4 >= NSTG) ? stage + 4 - NSTG : stage + 4;
            const char* bs = (const char*)(g_eB2 + (size_t)(nb2 * 128) * 512);
#pragma unroll
            for (int v = 0; v < 4; v++) {
                int idx = tid + v * 256;
                int r = idx >> 3, j = idx & 7;
                cp16(sbB + st2 * 16384 + swz((r << 7) + (j << 4)),
                     bs + ((size_t)r * 512 + sl2 * 64 + j * 8) * 2);
            }
            CP_COMMIT();
        }
        stage = (stage + 1 == NSTG) ? 0 : stage + 1;
    }

    // ---- final argmin reduction (reuse A smem) ----
    __syncthreads();
    float* rv = (float*)smem;               // [128][4]
    int*   ri = (int*)(smem + 2048);        // [128][4]
#pragma unroll
    for (int s = 0; s < 8; s++) {
        float v = best[s];
        int   ix = bidx[s];
#pragma unroll
        for (int off = 1; off <= 2; off <<= 1) {
            float ov = __shfl_xor_sync(0xffffffffu, v, off);
            int   oi = __shfl_xor_sync(0xffffffffu, ix, off);
            if (ov < v || (ov == v && oi < ix)) { v = ov; ix = oi; }
        }
        if ((lane & 3) == 0) {
            int row = wm * 64 + (s >> 1) * 16 + (lane >> 2) + (s & 1) * 8;
            rv[row * 4 + wn] = v;
            ri[row * 4 + wn] = ix;
        }
    }
    __syncthreads();
    if (tid < 128) {
        float bv = rv[tid * 4];
        int   bi = ri[tid * 4];
        for (int t = 1; t < 4; t++) {
            float v = rv[tid * 4 + t];
            int   i = ri[tid * 4 + t];
            if (v < bv || (v == bv && i < bi)) { bv = v; bi = i; }
        }
        g_idx[rowBase + tid]  = bi;
        g_best[rowBase + tid] = bv;
    }
}

// ---------------- K7: gather q, output, loss, counts, idx ------------------------
__global__ void k_quant(const int* __restrict__ mask,
                        float* __restrict__ outQ, float* __restrict__ outIdx) {
    int w = threadIdx.x >> 5, lane = threadIdx.x & 31;
    int row = blockIdx.x * 8 + w;
    int m = mask[row];
    int idx = g_idx[row];
    const float4* qv = (const float4*)&g_ET[(size_t)idx * DDIM];
    float4* ov = (float4*)&outQ[(size_t)row * DDIM];
    float4 z = make_float4(0.f, 0.f, 0.f, 0.f);
#pragma unroll
    for (int t = 0; t < 2; t++) {
        int j = lane + t * 32;
        ov[j] = m ? qv[j] : z;
    }
    __shared__ float red[8];
    if (lane == 0) {
        red[w] = m ? (g_xsq[row] + g_best[row]) : 0.f;
        outIdx[row] = m ? (float)idx : -1.f;
        if (m) atomicAdd(&g_counts[idx], 1.f);
    }
    __syncthreads();
    if (threadIdx.x == 0) {
        float t = 0.f;
        for (int i = 0; i < 8; i++) t += red[i];
        atomicAdd(&g_loss, (double)t);
    }
}

// ---------------- K8: finalize scalars ---------------------------------------------
__global__ void k_final(float* __restrict__ out) {
    int t = threadIdx.x;  // 1024 threads
    float nv = fmaxf(g_cnt, 1.f);
    float p = g_counts[t] / nv;
    float h = -p * logf(p + 1e-10f);
    for (int o = 16; o; o >>= 1) h += __shfl_down_sync(0xffffffffu, h, o);
    __shared__ float red[32];
    if ((t & 31) == 0) red[t >> 5] = h;
    __syncthreads();
    if (t < 32) {
        float s = red[t];
        for (int o = 16; o; o >>= 1) s += __shfl_down_sync(0xffffffffu, s, o);
        if (t == 0) {
            float loss = (float)(g_loss / ((double)nv * (double)DDIM));
            out[OFF_DICT]   = loss;
            out[OFF_COMMIT] = loss;
            out[OFF_PERP]   = expf(s);
        }
    }
}

// ---------------- launch --------------------------------------------------------------
extern "C" void kernel_launch(void* const* d_in, const int* in_sizes, int n_in,
                              void* d_out, int out_size) {
    const float* x     = (const float*)d_in[0];
    const int*   mask  = (const int*)  d_in[1];
    const float* E     = (const float*)d_in[2];
    const float* gamma = (const float*)d_in[3];
    const float* beta  = (const float*)d_in[4];
    float* out = (float*)d_out;

    cudaFuncSetAttribute(k_mma_argmin, cudaFuncAttributeMaxDynamicSharedMemorySize, SMEMSZ);

    k_zero<<<4, 256>>>();                                    // 1
    k_stats<<<256, dim3(64, 4)>>>(x, mask);                  // 2
    k_reduce_stats<<<1, 256>>>(gamma, beta);                 // 3
    k_splitx<<<BNROWS * 64 / 256, 256>>>(x);                 // 4
    k_prep_e<<<dim3(32, 8), dim3(32, 8)>>>(E);               // 5
    k_mma_argmin<<<BNROWS / 128, 256, SMEMSZ>>>();           // 6  (ncu -s 5 lands here)
    k_quant<<<BNROWS / 8, 256>>>(mask, out + OFF_Q, out + OFF_IDX);
    k_final<<<1, 1024>>>(out);
}

// round 5
// speedup vs baseline: 2.4277x; 1.0325x over previous
#include <cuda_runtime.h>
#include <cuda_fp16.h>
#include <cstdint>
#include <math.h>

// Problem dims
#define BNROWS 32768   // B*N
#define DDIM   256
#define KCODES 1024

// Output layout (float32, reference return order)
#define OFF_Q      0ull
#define OFF_DICT   8388608ull
#define OFF_COMMIT 8388609ull
#define OFF_IDX    8388610ull
#define OFF_PERP   8421378ull

// ---------------- scratch (device globals) -----------------------------------
__device__ float  g_partS [256][DDIM];
__device__ float  g_partS2[256][DDIM];
__device__ float  g_partC [256];
__device__ float  g_cnt;
__device__ __align__(16) float g_scale[DDIM];
__device__ __align__(16) float g_shift[DDIM];
__device__ __align__(16) __half g_eB2[(size_t)KCODES * 512]; // [e_h(256) | e_l(256)]
__device__ __align__(16) float g_ET[(size_t)KCODES * DDIM];  // codebook^T [K][D]
__device__ __align__(16) float g_csq[KCODES];
__device__ float  g_xsq[BNROWS];
__device__ unsigned long long g_packed[BNROWS];   // (monotone(dist)<<32)|idx
__device__ float  g_counts[KCODES];
__device__ double g_loss;
__device__ int    g_ticket;

// ---------------- helpers ------------------------------------------------------
__device__ __forceinline__ uint32_t s2u(const void* p) {
    uint32_t a;
    asm("{ .reg .u64 t; cvta.to.shared.u64 t, %1; cvt.u32.u64 %0, t; }" : "=r"(a) : "l"(p));
    return a;
}
__device__ __forceinline__ uint32_t swz(uint32_t off) { return off ^ ((off >> 3) & 0x70); }

__device__ __forceinline__ void cp16(uint32_t dst, const void* src) {
    asm volatile("cp.async.cg.shared.global [%0], [%1], 16;" :: "r"(dst), "l"(src) : "memory");
}
#define CP_COMMIT() asm volatile("cp.async.commit_group;" ::: "memory")
#define CP_WAIT(N)  asm volatile("cp.async.wait_group %0;" :: "n"(N) : "memory")

__device__ __forceinline__ void ldsm_x4(uint32_t* r, uint32_t addr) {
    asm volatile("ldmatrix.sync.aligned.m8n8.x4.shared.b16 {%0,%1,%2,%3}, [%4];"
                 : "=r"(r[0]), "=r"(r[1]), "=r"(r[2]), "=r"(r[3]) : "r"(addr));
}
__device__ __forceinline__ void ldsm_x2(uint32_t* r, uint32_t addr) {
    asm volatile("ldmatrix.sync.aligned.m8n8.x2.shared.b16 {%0,%1}, [%2];"
                 : "=r"(r[0]), "=r"(r[1]) : "r"(addr));
}
__device__ __forceinline__ void mma16816(float* c, const uint32_t* a, const uint32_t* b) {
    asm volatile(
        "mma.sync.aligned.m16n8k16.row.col.f32.f16.f16.f32 "
        "{%0,%1,%2,%3}, {%4,%5,%6,%7}, {%8,%9}, {%0,%1,%2,%3};"
        : "+f"(c[0]), "+f"(c[1]), "+f"(c[2]), "+f"(c[3])
        : "r"(a[0]), "r"(a[1]), "r"(a[2]), "r"(a[3]), "r"(b[0]), "r"(b[1]));
}

// ---------------- K1: masked stats partials + init packed/csq -------------------
__global__ void k_stats(const float* __restrict__ x, const int* __restrict__ mask) {
    int d4 = threadIdx.x;   // 0..63 (float4 columns)
    int ty = threadIdx.y;   // 0..3
    int b  = blockIdx.x;
    int gid = b * 256 + ty * 64 + d4;
    if (gid < BNROWS) g_packed[gid] = 0xFFFFFFFFFFFFFFFFull;
    if (gid < KCODES) g_csq[gid] = 0.f;

    int r0 = b * 128 + ty * 32;
    const float4* x4 = (const float4*)x;
    float4 s  = make_float4(0.f, 0.f, 0.f, 0.f);
    float4 s2 = make_float4(0.f, 0.f, 0.f, 0.f);
    float  c  = 0.f;
    for (int r = 0; r < 32; r++) {
        if (mask[r0 + r]) {
            float4 v = x4[(size_t)(r0 + r) * 64 + d4];
            s.x += v.x; s.y += v.y; s.z += v.z; s.w += v.w;
            s2.x += v.x * v.x; s2.y += v.y * v.y; s2.z += v.z * v.z; s2.w += v.w * v.w;
            c += 1.f;
        }
    }
    __shared__ float4 sS[4][64], sS2[4][64];
    __shared__ float  sC[4];
    sS[ty][d4] = s; sS2[ty][d4] = s2;
    if (d4 == 0) sC[ty] = c;
    __syncthreads();
    if (ty == 0) {
        for (int y = 1; y < 4; y++) {
            float4 a = sS[y][d4], a2 = sS2[y][d4];
            s.x += a.x; s.y += a.y; s.z += a.z; s.w += a.w;
            s2.x += a2.x; s2.y += a2.y; s2.z += a2.z; s2.w += a2.w;
        }
        ((float4*)g_partS [b])[d4] = s;
        ((float4*)g_partS2[b])[d4] = s2;
        if (d4 == 0) g_partC[b] = sC[0] + sC[1] + sC[2] + sC[3];
    }
}

// ---------------- K2: transpose E + fp16 split + csq partials --------------------
__global__ void k_prep_e(const float* __restrict__ E) {
    __shared__ float t[32][33];
    int tx = threadIdx.x, ty = threadIdx.y;
    int x0 = blockIdx.x * 32;  // code
    int y0 = blockIdx.y * 32;  // d
    for (int j = ty; j < 32; j += 8)
        t[j][tx] = E[(size_t)(y0 + j) * KCODES + x0 + tx];
    __syncthreads();
    for (int j = ty; j < 32; j += 8) {
        int code = x0 + j, d = y0 + tx;
        float v = t[tx][j];
        g_ET[(size_t)code * DDIM + d] = v;
        __half h = __float2half_rn(v);
        g_eB2[(size_t)code * 512 + d]       = h;
        g_eB2[(size_t)code * 512 + 256 + d] = __float2half_rn(v - __half2float(h));
        float sq = v * v;
        for (int o = 16; o; o >>= 1) sq += __shfl_down_sync(0xffffffffu, sq, o);
        if (tx == 0) atomicAdd(&g_csq[code], sq);
    }
}

// ---------------- K3: reduce stats -> scale/shift; zero counts/loss/ticket -------
__global__ void k_reduce_stats(const float* __restrict__ gamma, const float* __restrict__ beta) {
    int d = threadIdx.x;
    float s = 0.f, s2 = 0.f, cnt = 0.f;
#pragma unroll 8
    for (int b = 0; b < 256; b++) {
        s  += g_partS [b][d];
        s2 += g_partS2[b][d];
        cnt += g_partC[b];
    }
    for (int i = d; i < KCODES; i += 256) g_counts[i] = 0.f;
    if (d == 0) { g_cnt = cnt; g_loss = 0.0; g_ticket = 0; }
    float nv = fmaxf(cnt, 1.f);
    float mu  = s / nv;
    float var = s2 / nv - mu * mu;
    float sc  = rsqrtf(var + 1e-5f) * gamma[d];
    g_scale[d] = sc;
    g_shift[d] = beta[d] - mu * sc;
}

// ---------------- K4: persistent HMMA GEMM + argmin -------------------------------
// 1024 tiles = 256 row-tiles (128 rows) x 4 code-tiles (256 codes), atomic ticket,
// code-major order so consecutive tickets reuse resident A. A built in-kernel from
// x (BN scale/shift + fp16 hi/lo split + ||xb||^2). B: 16 chunks/tile, 5-stage ring.
#define NTILES  1024
#define B_OFF   131072
#define NSTG    5
#define CSQ_OFF (B_OFF + NSTG * 16384)    // 212992
#define XSQ_OFF (CSQ_OFF + 4096)          // 217088
#define RV_OFF  (XSQ_OFF + 1024)          // 218112
#define RI_OFF  (RV_OFF + 2048)           // 220160
#define TK_OFF  (RI_OFF + 2048)           // 222208
#define SMEMSZ  (TK_OFF + 16)             // 222224

__global__ void __launch_bounds__(256, 1) k_mma_argmin(const float* __restrict__ x) {
    extern __shared__ char smem[];
    const uint32_t sbA = s2u(smem);
    const uint32_t sbB = sbA + B_OFF;
    const int tid  = threadIdx.x;
    const int lane = tid & 31;
    const int wid  = tid >> 5;
    const int wm   = wid >> 2;       // 0..1
    const int wn   = wid & 3;        // 0..3

    // csq -> smem (1024 floats)
    ((float4*)(smem + CSQ_OFF))[tid] = ((const float4*)g_csq)[tid];
    int*   s_tk  = (int*)(smem + TK_OFF);
    float* sxsq  = (float*)(smem + XSQ_OFF);
    float* rv    = (float*)(smem + RV_OFF);   // [128][4]
    int*   ri    = (int*)(smem + RI_OFF);     // [128][4]
    const float* scsq = (const float*)(smem + CSQ_OFF);

    // per-thread fixed A column (for conversion)
    const int colA = tid & 63;
    const float4 scv = ((const float4*)g_scale)[colA];
    const float4 shv = ((const float4*)g_shift)[colA];

    const uint32_t aRow = (uint32_t)(wm * 64 + (lane & 15));
    const uint32_t aKG  = (uint32_t)((lane >> 4) << 4);
    const uint32_t bRow = (uint32_t)(wn * 32 + (lane & 7));
    const uint32_t bKG  = (uint32_t)(((lane >> 3) & 1) << 4);

    int cachedRow = -1;
    for (;;) {
        __syncthreads();
        if (tid == 0) *s_tk = atomicAdd(&g_ticket, 1);
        __syncthreads();
        const int tk = *s_tk;
        if (tk >= NTILES) break;
        const int rowTile  = tk >> 2;
        const int codeTile = tk & 3;
        const int rowBase  = rowTile << 7;
        const int codeBase = codeTile << 8;

        // ---- B prologue: chunks 0..3 (nsub=0, sl=0..3) into stages 0..3 ----
        {
            const char* bs = (const char*)(g_eB2 + (size_t)codeBase * 512);
#pragma unroll
            for (int c0 = 0; c0 < 4; c0++) {
#pragma unroll
                for (int v = 0; v < 4; v++) {
                    int idx = tid + v * 256;
                    int r = idx >> 3, j = idx & 7;
                    cp16(sbB + c0 * 16384 + swz((r << 7) + (j << 4)),
                         bs + ((size_t)r * 512 + c0 * 64 + j * 8) * 2);
                }
                CP_COMMIT();
            }
        }

        // ---- A load/convert (only when row-tile changes) ----
        if (rowTile != cachedRow) {
            cachedRow = rowTile;
            const float4* xs = (const float4*)(x + (size_t)rowBase * DDIM);
            const int kk = colA >> 4, jj = colA & 15;
            const uint32_t offh = sbA + kk * 16384;
#pragma unroll 4
            for (int i = 0; i < 32; i++) {
                int r = (tid >> 6) + i * 4;
                float4 v = xs[(size_t)r * 64 + colA];
                float b0 = v.x * scv.x + shv.x;
                float b1 = v.y * scv.y + shv.y;
                float b2 = v.z * scv.z + shv.z;
                float b3 = v.w * scv.w + shv.w;
                __half2 h01 = __floats2half2_rn(b0, b1);
                __half2 h23 = __floats2half2_rn(b2, b3);
                __half2 l01 = __floats2half2_rn(b0 - __low2float(h01), b1 - __high2float(h01));
                __half2 l23 = __floats2half2_rn(b2 - __low2float(h23), b3 - __high2float(h23));
                uint32_t so = swz((uint32_t)(r << 7) + (jj << 3));
                asm volatile("st.shared.v2.u32 [%0], {%1,%2};"
                             :: "r"(offh + so), "r"(*(uint32_t*)&h01), "r"(*(uint32_t*)&h23));
                asm volatile("st.shared.v2.u32 [%0], {%1,%2};"
                             :: "r"(offh + 65536 + so), "r"(*(uint32_t*)&l01), "r"(*(uint32_t*)&l23));
                float s = b0 * b0 + b1 * b1 + b2 * b2 + b3 * b3;
                for (int o = 16; o; o >>= 1) s += __shfl_down_sync(0xffffffffu, s, o);
                if (lane == 0) sxsq[r * 2 + (wid & 1)] = s;
            }
            __syncthreads();
            if (tid < 128) g_xsq[rowBase + tid] = sxsq[tid * 2] + sxsq[tid * 2 + 1];
        }

        // ---- mainloop: 16 chunks (2 n-subtiles x 8) ----
        float acc[4][4][4];
        float best[8];
        int   bidx[8];
#pragma unroll
        for (int s = 0; s < 8; s++) { best[s] = 3.4e38f; bidx[s] = 0; }

        int stage = 0;
#pragma unroll 1
        for (int c = 0; c < 16; c++) {
            const int nsub = c >> 3;
            const int sl = c & 7;
            const int kk2 = sl & 3;
            const bool dual = (sl < 4);

            if (c <= 12)      CP_WAIT(3);
            else if (c == 13) CP_WAIT(2);
            else if (c == 14) CP_WAIT(1);
            else              CP_WAIT(0);
            __syncthreads();

            if (sl == 0) {
#pragma unroll
                for (int mf = 0; mf < 4; mf++)
#pragma unroll
                    for (int nf = 0; nf < 4; nf++)
#pragma unroll
                        for (int t = 0; t < 4; t++) acc[mf][nf][t] = 0.f;
            }

            const uint32_t bbase = sbB + stage * 16384;
            const uint32_t ah = sbA + kk2 * 16384;
            const uint32_t al = ah + 65536;
#pragma unroll
            for (int ks = 0; ks < 4; ks++) {
                uint32_t b[4][2];
#pragma unroll
                for (int nf = 0; nf < 4; nf++)
                    ldsm_x2(b[nf], bbase + swz(((bRow + nf * 8) << 7) + ks * 32 + bKG));
                uint32_t a[4][4];
#pragma unroll
                for (int mf = 0; mf < 4; mf++)
                    ldsm_x4(a[mf], ah + swz(((aRow + mf * 16) << 7) + ks * 32 + aKG));
#pragma unroll
                for (int mf = 0; mf < 4; mf++)
#pragma unroll
                    for (int nf = 0; nf < 4; nf++)
                        mma16816(acc[mf][nf], a[mf], b[nf]);
                if (dual) {
                    uint32_t a2[4][4];
#pragma unroll
                    for (int mf = 0; mf < 4; mf++)
                        ldsm_x4(a2[mf], al + swz(((aRow + mf * 16) << 7) + ks * 32 + aKG));
#pragma unroll
                    for (int mf = 0; mf < 4; mf++)
#pragma unroll
                        for (int nf = 0; nf < 4; nf++)
                            mma16816(acc[mf][nf], a2[mf], b[nf]);
                }
            }

            if (sl == 7) {
                const float* csqp = scsq + codeBase + nsub * 128 + wn * 32 + 2 * (lane & 3);
#pragma unroll
                for (int nf = 0; nf < 4; nf++) {
                    float q0 = csqp[nf * 8];
                    float q1 = csqp[nf * 8 + 1];
                    int n0 = codeBase + nsub * 128 + wn * 32 + nf * 8 + 2 * (lane & 3);
#pragma unroll
                    for (int mf = 0; mf < 4; mf++) {
                        float d0 = q0 - 2.f * acc[mf][nf][0];
                        float d1 = q1 - 2.f * acc[mf][nf][1];
                        float d2 = q0 - 2.f * acc[mf][nf][2];
                        float d3 = q1 - 2.f * acc[mf][nf][3];
                        int s0 = mf * 2, s1 = mf * 2 + 1;
                        if (d0 < best[s0]) { best[s0] = d0; bidx[s0] = n0; }
                        if (d1 < best[s0]) { best[s0] = d1; bidx[s0] = n0 + 1; }
                        if (d2 < best[s1]) { best[s1] = d2; bidx[s1] = n0; }
                        if (d3 < best[s1]) { best[s1] = d3; bidx[s1] = n0 + 1; }
                    }
                }
            }

            if (c + 4 < 16) {
                const int cc = c + 4;
                const int nsub2 = cc >> 3, sl2 = cc & 7;
                const int st2 = (stage + 4 >= NSTG) ? stage + 4 - NSTG : stage + 4;
                const char* bs = (const char*)(g_eB2 + (size_t)(codeBase + nsub2 * 128) * 512);
#pragma unroll
                for (int v = 0; v < 4; v++) {
                    int idx = tid + v * 256;
                    int r = idx >> 3, j = idx & 7;
                    cp16(sbB + st2 * 16384 + swz((r << 7) + (j << 4)),
                         bs + ((size_t)r * 512 + sl2 * 64 + j * 8) * 2);
                }
                CP_COMMIT();
            }
            stage = (stage + 1 == NSTG) ? 0 : stage + 1;
        }

        // ---- per-tile argmin reduce + global merge ----
        __syncthreads();
#pragma unroll
        for (int s = 0; s < 8; s++) {
            float v = best[s];
            int   ix = bidx[s];
#pragma unroll
            for (int off = 1; off <= 2; off <<= 1) {
                float ov = __shfl_xor_sync(0xffffffffu, v, off);
                int   oi = __shfl_xor_sync(0xffffffffu, ix, off);
                if (ov < v || (ov == v && oi < ix)) { v = ov; ix = oi; }
            }
            if ((lane & 3) == 0) {
                int row = wm * 64 + (s >> 1) * 16 + (lane >> 2) + (s & 1) * 8;
                rv[row * 4 + wn] = v;
                ri[row * 4 + wn] = ix;
            }
        }
        __syncthreads();
        if (tid < 128) {
            float bv = rv[tid * 4];
            int   bi = ri[tid * 4];
#pragma unroll
            for (int t = 1; t < 4; t++) {
                float v = rv[tid * 4 + t];
                int   i = ri[tid * 4 + t];
                if (v < bv || (v == bv && i < bi)) { bv = v; bi = i; }
            }
            unsigned ub = __float_as_uint(bv);
            unsigned key = ((int)ub < 0) ? ~ub : (ub | 0x80000000u);
            unsigned long long pk = ((unsigned long long)key << 32) | (unsigned)bi;
            atomicMin(&g_packed[rowBase + tid], pk);
        }
    }
}

// ---------------- K5: gather q, output, loss, counts, idx --------------------------
__global__ void k_quant(const int* __restrict__ mask,
                        float* __restrict__ outQ, float* __restrict__ outIdx) {
    int w = threadIdx.x >> 5, lane = threadIdx.x & 31;
    int row = blockIdx.x * 8 + w;
    int m = mask[row];
    unsigned long long pk = g_packed[row];
    int idx = (int)(pk & 0xffffffffull);
    const float4* qv = (const float4*)&g_ET[(size_t)idx * DDIM];
    float4* ov = (float4*)&outQ[(size_t)row * DDIM];
    float4 z = make_float4(0.f, 0.f, 0.f, 0.f);
#pragma unroll
    for (int t = 0; t < 2; t++) {
        int j = lane + t * 32;
        ov[j] = m ? qv[j] : z;
    }
    __shared__ float red[8];
    if (lane == 0) {
        unsigned key = (unsigned)(pk >> 32);
        unsigned ub = (key & 0x80000000u) ? (key & 0x7fffffffu) : ~key;
        float best = __uint_as_float(ub);
        red[w] = m ? (g_xsq[row] + best) : 0.f;
        outIdx[row] = m ? (float)idx : -1.f;
        if (m) atomicAdd(&g_counts[idx], 1.f);
    }
    __syncthreads();
    if (threadIdx.x == 0) {
        float t = 0.f;
        for (int i = 0; i < 8; i++) t += red[i];
        atomicAdd(&g_loss, (double)t);
    }
}

// ---------------- K6: finalize scalars -----------------------------------------------
__global__ void k_final(float* __restrict__ out) {
    int t = threadIdx.x;  // 1024 threads
    float nv = fmaxf(g_cnt, 1.f);
    float p = g_counts[t] / nv;
    float h = -p * logf(p + 1e-10f);
    for (int o = 16; o; o >>= 1) h += __shfl_down_sync(0xffffffffu, h, o);
    __shared__ float red[32];
    if ((t & 31) == 0) red[t >> 5] = h;
    __syncthreads();
    if (t < 32) {
        float s = red[t];
        for (int o = 16; o; o >>= 1) s += __shfl_down_sync(0xffffffffu, s, o);
        if (t == 0) {
            float loss = (float)(g_loss / ((double)nv * (double)DDIM));
            out[OFF_DICT]   = loss;
            out[OFF_COMMIT] = loss;
            out[OFF_PERP]   = expf(s);
        }
    }
}

// ---------------- launch ----------------------------------------------------------------
extern "C" void kernel_launch(void* const* d_in, const int* in_sizes, int n_in,
                              void* d_out, int out_size) {
    const float* x     = (const float*)d_in[0];
    const int*   mask  = (const int*)  d_in[1];
    const float* E     = (const float*)d_in[2];
    const float* gamma = (const float*)d_in[3];
    const float* beta  = (const float*)d_in[4];
    float* out = (float*)d_out;

    cudaFuncSetAttribute(k_mma_argmin, cudaFuncAttributeMaxDynamicSharedMemorySize, SMEMSZ);

    k_stats<<<256, dim3(64, 4)>>>(x, mask);                  // 1
    k_prep_e<<<dim3(32, 8), dim3(32, 8)>>>(E);               // 2
    k_reduce_stats<<<1, 256>>>(gamma, beta);                 // 3
    k_mma_argmin<<<148, 256, SMEMSZ>>>(x);                   // 4  (ncu lands here)
    k_quant<<<BNROWS / 8, 256>>>(mask, out + OFF_Q, out + OFF_IDX);
    k_final<<<1, 1024>>>(out);
}